// round 2
// baseline (speedup 1.0000x reference)
#include <cuda_runtime.h>
#include <cuda_bf16.h>
#include <math.h>

// MSRSA fused attention, fp32 SIMT baseline.
// B=2, H=16, L=2048, D=128.
// One CTA = (b, h, 16-query tile). Scores for the full 16x2048 row block are
// materialized in shared memory, softmaxed in place, written to the attn
// output exactly once, then P·V is accumulated from smem with 1/rowsum folded
// into the output epilogue.
//
// Grid ordering: h innermost, so the 16 heads that share A/D rows run
// back-to-back and hit L2 for adjacency / distance matrices.

#define Bq 2
#define Hh 16
#define Ll 2048
#define Dd 128
#define QT 16
#define KT 64
#define NTHREADS 256
#define KROW 132              // padded K/V tile row stride in floats (33 x 16B -> conflict-free LDS.128)
#define INV_SCALE 0.08838834764831845f   // 1/sqrt(128)

__global__ void __launch_bounds__(NTHREADS)
msrsa_fused_kernel(const float* __restrict__ Q,
                   const float* __restrict__ K,
                   const float* __restrict__ V,
                   const float* __restrict__ A,
                   const float* __restrict__ Ds,
                   const float* __restrict__ wA,
                   const float* __restrict__ wD,
                   float* __restrict__ out,
                   float* __restrict__ attn) {
    extern __shared__ float sm[];
    float* Qs  = sm;                    // QT*Dd = 2048 floats
    float* KVs = sm + QT * Dd;          // KT*KROW = 8448 floats
    float* S   = KVs + KT * KROW;       // QT*Ll = 32768 floats
    __shared__ float s_inv[QT];

    const int t  = threadIdx.x;
    const int bx = blockIdx.x;
    const int h    = bx & (Hh - 1);
    const int rest = bx >> 4;
    const int qt   = rest & (Ll / QT - 1);
    const int b    = rest >> 7;
    const int q0   = qt * QT;

    const size_t bh = (size_t)(b * Hh + h);
    const float* Qb = Q + (bh * Ll + q0) * Dd;
    const float* Kb = K + bh * Ll * Dd;
    const float* Vb = V + bh * Ll * Dd;
    const float* Ab = A  + ((size_t)b * Ll + q0) * Ll;
    const float* Db = Ds + ((size_t)b * Ll + q0) * Ll;
    const float wa = wA[h];
    const float wd = wD[h];

    // ---- load Q tile (16x128, contiguous) ----
    {
        const float4* Qg4 = (const float4*)Qb;
        float4* Qs4 = (float4*)Qs;
        #pragma unroll
        for (int i = t; i < QT * Dd / 4; i += NTHREADS) Qs4[i] = Qg4[i];
    }

    const int qy = t >> 5;   // 0..7 : handles q rows {qy, qy+8}
    const int kx = t & 31;   // 0..31: handles k cols {kx, kx+32} within tile

    const float4* Qs4 = (const float4*)Qs;
    const float4* K4  = (const float4*)KVs;   // row stride 33 float4

    // ============ Phase 1: logits -> S ============
    for (int kt = 0; kt < Ll / KT; ++kt) {
        const int k0 = kt * KT;
        __syncthreads();
        // load K tile 64x128
        {
            const float4* Kg4 = (const float4*)(Kb + (size_t)k0 * Dd);
            #pragma unroll
            for (int i = t; i < KT * (Dd / 4); i += NTHREADS) {
                int r = i >> 5, c = i & 31;
                *(float4*)&KVs[r * KROW + c * 4] = Kg4[i];
            }
        }
        __syncthreads();

        float a00 = 0.f, a01 = 0.f, a10 = 0.f, a11 = 0.f;
        #pragma unroll
        for (int d4 = 0; d4 < Dd / 4; ++d4) {
            float4 qa = Qs4[qy * 32 + d4];
            float4 qb = Qs4[(qy + 8) * 32 + d4];
            float4 ka = K4[kx * 33 + d4];
            float4 kb = K4[(kx + 32) * 33 + d4];
            a00 += qa.x * ka.x + qa.y * ka.y + qa.z * ka.z + qa.w * ka.w;
            a01 += qa.x * kb.x + qa.y * kb.y + qa.z * kb.z + qa.w * kb.w;
            a10 += qb.x * ka.x + qb.y * ka.y + qb.z * ka.z + qb.w * ka.w;
            a11 += qb.x * kb.x + qb.y * kb.y + qb.z * kb.z + qb.w * kb.w;
        }

        // apply (1 + A*wa + D*wd)/scale, store logits
        {
            const int gk0 = k0 + kx, gk1 = k0 + kx + 32;
            const size_t r0 = (size_t)qy * Ll;
            const size_t r1 = (size_t)(qy + 8) * Ll;
            float m;
            m = 1.f + Ab[r0 + gk0] * wa + Db[r0 + gk0] * wd;
            S[qy * Ll + gk0] = a00 * m * INV_SCALE;
            m = 1.f + Ab[r0 + gk1] * wa + Db[r0 + gk1] * wd;
            S[qy * Ll + gk1] = a01 * m * INV_SCALE;
            m = 1.f + Ab[r1 + gk0] * wa + Db[r1 + gk0] * wd;
            S[(qy + 8) * Ll + gk0] = a10 * m * INV_SCALE;
            m = 1.f + Ab[r1 + gk1] * wa + Db[r1 + gk1] * wd;
            S[(qy + 8) * Ll + gk1] = a11 * m * INV_SCALE;
        }
    }
    __syncthreads();

    // ============ Phase 2: softmax in smem (warp w owns rows w, w+8) ============
    {
        const int w    = t >> 5;
        const int lane = t & 31;
        #pragma unroll
        for (int rsel = 0; rsel < 2; ++rsel) {
            const int rr = w + rsel * 8;
            float* row = S + rr * Ll;
            float m = -1e30f;
            for (int c = lane; c < Ll; c += 32) m = fmaxf(m, row[c]);
            #pragma unroll
            for (int o = 16; o > 0; o >>= 1) m = fmaxf(m, __shfl_xor_sync(0xffffffffu, m, o));
            float sum = 0.f;
            for (int c = lane; c < Ll; c += 32) {
                float e = __expf(row[c] - m);
                row[c] = e;
                sum += e;
            }
            #pragma unroll
            for (int o = 16; o > 0; o >>= 1) sum += __shfl_xor_sync(0xffffffffu, sum, o);
            if (lane == 0) s_inv[rr] = 1.f / sum;
        }
    }
    __syncthreads();

    // ============ Phase 3: write normalized attention weights ============
    {
        float* attn_base = attn + (bh * Ll + q0) * Ll;   // QT x L contiguous block
        const float4* S4 = (const float4*)S;
        float4* O4 = (float4*)attn_base;
        #pragma unroll 4
        for (int i = t; i < QT * Ll / 4; i += NTHREADS) {
            const int row = i >> 9;                      // 512 float4 per row
            const float inv = s_inv[row];
            float4 v = S4[i];
            v.x *= inv; v.y *= inv; v.z *= inv; v.w *= inv;
            O4[i] = v;
        }
    }

    // ============ Phase 4: out = (E / rowsum) @ V ============
    {
        const int dx = t & 31;    // d chunk (float4)
        float4 o0 = make_float4(0.f, 0.f, 0.f, 0.f);
        float4 o1 = make_float4(0.f, 0.f, 0.f, 0.f);
        for (int kt = 0; kt < Ll / KT; ++kt) {
            const int k0 = kt * KT;
            __syncthreads();
            {
                const float4* Vg4 = (const float4*)(Vb + (size_t)k0 * Dd);
                #pragma unroll
                for (int i = t; i < KT * (Dd / 4); i += NTHREADS) {
                    int r = i >> 5, c = i & 31;
                    *(float4*)&KVs[r * KROW + c * 4] = Vg4[i];
                }
            }
            __syncthreads();
            const float* Srow0 = S + qy * Ll + k0;
            const float* Srow1 = S + (qy + 8) * Ll + k0;
            #pragma unroll 8
            for (int k = 0; k < KT; ++k) {
                const float w0 = Srow0[k];
                const float w1 = Srow1[k];
                const float4 v = K4[k * 33 + dx];
                o0.x += w0 * v.x; o0.y += w0 * v.y; o0.z += w0 * v.z; o0.w += w0 * v.w;
                o1.x += w1 * v.x; o1.y += w1 * v.y; o1.z += w1 * v.z; o1.w += w1 * v.w;
            }
        }
        const float i0 = s_inv[qy];
        const float i1 = s_inv[qy + 8];
        o0.x *= i0; o0.y *= i0; o0.z *= i0; o0.w *= i0;
        o1.x *= i1; o1.y *= i1; o1.z *= i1; o1.w *= i1;
        float* outb = out + (bh * Ll + q0) * Dd;
        ((float4*)(outb + qy * Dd))[dx] = o0;
        ((float4*)(outb + (qy + 8) * Dd))[dx] = o1;
    }
}

extern "C" void kernel_launch(void* const* d_in, const int* in_sizes, int n_in,
                              void* d_out, int out_size) {
    (void)in_sizes; (void)n_in;
    const float* Q  = (const float*)d_in[0];
    const float* K  = (const float*)d_in[1];
    const float* V  = (const float*)d_in[2];
    const float* A  = (const float*)d_in[3];
    const float* Ds = (const float*)d_in[4];
    const float* wA = (const float*)d_in[5];
    const float* wD = (const float*)d_in[6];

    float* out  = (float*)d_out;                          // B*H*L*D = 8388608 floats
    float* attn = (float*)d_out + (size_t)Bq * Hh * Ll * Dd; // then B*H*L*L
    (void)out_size;

    const size_t smem = (size_t)(QT * Dd + KT * KROW + QT * Ll) * sizeof(float); // 173056 B
    cudaFuncSetAttribute(msrsa_fused_kernel,
                         cudaFuncAttributeMaxDynamicSharedMemorySize, (int)smem);

    dim3 grid(Bq * Hh * (Ll / QT));  // 4096 CTAs, h innermost
    msrsa_fused_kernel<<<grid, NTHREADS, smem>>>(Q, K, V, A, Ds, wA, wD, out, attn);
}

// round 3
// speedup vs baseline: 2.1766x; 2.1766x over previous
#include <cuda_runtime.h>
#include <cuda_bf16.h>
#include <stdint.h>

// MSRSA fused attention — bf16x3 tensor-core version.
// B=2, H=16, L=2048, D=128.
// Prep kernels split K (row-major) and V (transposed [d][n]) into hi/lo bf16
// device-global scratch. Main kernel: one CTA per (b,h,16-query tile);
// logits via mma.sync bf16 (3-term split), softmax + attn write from smem,
// PV via mma.sync with in-place packed hi/lo conversion of exp values.

#define Bq 2
#define Hh 16
#define Ll 2048
#define Dd 128
#define QT 16
#define NTHREADS 256
#define SPITCH 2056                       // S row pitch in f32 words (2-way-conflict stores)
#define INV_SCALE 0.08838834764831845f    // 1/sqrt(128)

#define KTILE 64
#define NKT (Ll / KTILE)                  // 32
#define KPITCH 136                        // K tile row pitch (bf16 units)
#define VPITCH 72                         // Vt tile row pitch (bf16 units)
#define STAGE_BYTES 36864                 // max(K stage 34816, V stage 36864)
#define SMEM_BYTES (QT * SPITCH * 4 + 2 * STAGE_BYTES)   // 131584 + 73728 = 205312

#define NELEM ((size_t)Bq * Hh * Ll * Dd) // 8388608

__device__ __nv_bfloat16 g_Khi[NELEM];
__device__ __nv_bfloat16 g_Klo[NELEM];
__device__ __nv_bfloat16 g_Vthi[NELEM];   // [bh][d][n]
__device__ __nv_bfloat16 g_Vtlo[NELEM];

// ---------------- helpers ----------------
__device__ __forceinline__ void split2(float x, float y, uint32_t& hi, uint32_t& lo) {
    __nv_bfloat16 hx = __float2bfloat16_rn(x);
    __nv_bfloat16 hy = __float2bfloat16_rn(y);
    float rx = x - __bfloat162float(hx);
    float ry = y - __bfloat162float(hy);
    __nv_bfloat16 lx = __float2bfloat16_rn(rx);
    __nv_bfloat16 ly = __float2bfloat16_rn(ry);
    hi = (uint32_t)*(unsigned short*)&hx | ((uint32_t)*(unsigned short*)&hy << 16);
    lo = (uint32_t)*(unsigned short*)&lx | ((uint32_t)*(unsigned short*)&ly << 16);
}

__device__ __forceinline__ void mma16816(float c[4],
                                         uint32_t a0, uint32_t a1, uint32_t a2, uint32_t a3,
                                         uint32_t b0, uint32_t b1) {
    asm volatile(
        "mma.sync.aligned.m16n8k16.row.col.f32.bf16.bf16.f32 "
        "{%0,%1,%2,%3}, {%4,%5,%6,%7}, {%8,%9}, {%0,%1,%2,%3};\n"
        : "+f"(c[0]), "+f"(c[1]), "+f"(c[2]), "+f"(c[3])
        : "r"(a0), "r"(a1), "r"(a2), "r"(a3), "r"(b0), "r"(b1));
}

// ---------------- prep kernels ----------------
__global__ void prep_k_kernel(const float* __restrict__ K) {
    size_t i = (size_t)blockIdx.x * blockDim.x + threadIdx.x;   // one float4
    if (i >= NELEM / 4) return;
    float4 v = ((const float4*)K)[i];
    uint32_t h0, l0, h1, l1;
    split2(v.x, v.y, h0, l0);
    split2(v.z, v.w, h1, l1);
    ((uint2*)g_Khi)[i] = make_uint2(h0, h1);
    ((uint2*)g_Klo)[i] = make_uint2(l0, l1);
}

__global__ void prep_v_kernel(const float* __restrict__ V) {
    __shared__ float ts[32][33];
    const int tx = threadIdx.x, ty = threadIdx.y;    // (32, 8)
    const int k0 = blockIdx.x * 32;                  // 64 k-tiles
    const int d0 = blockIdx.y * 32;                  // 4 d-tiles
    const int bh = blockIdx.z;                       // 32
    const size_t vb = (size_t)bh * Ll * Dd;
    #pragma unroll
    for (int i = 0; i < 4; ++i)
        ts[ty + 8 * i][tx] = V[vb + (size_t)(k0 + ty + 8 * i) * Dd + d0 + tx];
    __syncthreads();
    #pragma unroll
    for (int i = 0; i < 4; ++i) {
        float x = ts[tx][ty + 8 * i];
        __nv_bfloat16 h = __float2bfloat16_rn(x);
        __nv_bfloat16 l = __float2bfloat16_rn(x - __bfloat162float(h));
        size_t o = (size_t)bh * Dd * Ll + (size_t)(d0 + ty + 8 * i) * Ll + k0 + tx;
        g_Vthi[o] = h;
        g_Vtlo[o] = l;
    }
}

// ---------------- main kernel ----------------
__global__ void __launch_bounds__(NTHREADS, 1)
msrsa_mma_kernel(const float* __restrict__ Q,
                 const float* __restrict__ A,
                 const float* __restrict__ Dm,
                 const float* __restrict__ wA,
                 const float* __restrict__ wD,
                 float* __restrict__ out,
                 float* __restrict__ attn) {
    extern __shared__ float sm[];
    float* S = sm;                                           // QT x SPITCH f32
    char* bufbase = (char*)sm + QT * SPITCH * 4;             // 2 x STAGE_BYTES
    __shared__ float s_inv[QT];

    const int t = threadIdx.x;
    const int w = t >> 5;
    const int lane = t & 31;
    const int g = lane >> 2;      // groupID 0..7
    const int tg = lane & 3;      // 0..3

    const int bx = blockIdx.x;
    const int h = bx & (Hh - 1);
    const int rest = bx >> 4;
    const int qt = rest & (Ll / QT - 1);
    const int b = rest >> 7;
    const int q0 = qt * QT;
    const size_t bh = (size_t)(b * Hh + h);

    const float* Qb = Q + (bh * Ll + q0) * Dd;
    const size_t adbase = ((size_t)b * Ll + q0) * Ll;
    const float wa = wA[h];
    const float wd = wD[h];
    const size_t kbase = bh * (size_t)Ll * Dd;       // element offset into g_Khi/g_Klo
    const size_t vbase = bh * (size_t)Dd * Ll;       // element offset into g_Vthi/g_Vtlo

    // ---- build Q fragments (held in registers for all of phase 1) ----
    uint32_t qh[8][4], ql[8][4];
    #pragma unroll
    for (int s = 0; s < 8; ++s) {
        const int c0 = 16 * s + 2 * tg;
        float2 p0 = *(const float2*)&Qb[g * Dd + c0];
        float2 p1 = *(const float2*)&Qb[(g + 8) * Dd + c0];
        float2 p2 = *(const float2*)&Qb[g * Dd + c0 + 8];
        float2 p3 = *(const float2*)&Qb[(g + 8) * Dd + c0 + 8];
        split2(p0.x, p0.y, qh[s][0], ql[s][0]);
        split2(p1.x, p1.y, qh[s][1], ql[s][1]);
        split2(p2.x, p2.y, qh[s][2], ql[s][2]);
        split2(p3.x, p3.y, qh[s][3], ql[s][3]);
    }

    uint4 stg[8];

    // ============ Phase 1: logits -> S via mma ============
    {
        // preload tile 0
        {
            const uint4* sh = (const uint4*)(g_Khi + kbase);
            const uint4* sl = (const uint4*)(g_Klo + kbase);
            #pragma unroll
            for (int j = 0; j < 4; ++j) { stg[j] = sh[t + j * 256]; stg[4 + j] = sl[t + j * 256]; }
            uint4* dh = (uint4*)(bufbase);
            uint4* dl = (uint4*)(bufbase + KTILE * KPITCH * 2);
            #pragma unroll
            for (int j = 0; j < 4; ++j) {
                int i = t + j * 256, r = i >> 4, c = i & 15;
                dh[r * 17 + c] = stg[j];
                dl[r * 17 + c] = stg[4 + j];
            }
        }
        __syncthreads();

        for (int kt = 0; kt < NKT; ++kt) {
            const int cb = kt & 1;
            if (kt + 1 < NKT) {
                const uint4* sh = (const uint4*)(g_Khi + kbase + (size_t)(kt + 1) * KTILE * Dd);
                const uint4* sl = (const uint4*)(g_Klo + kbase + (size_t)(kt + 1) * KTILE * Dd);
                #pragma unroll
                for (int j = 0; j < 4; ++j) { stg[j] = sh[t + j * 256]; stg[4 + j] = sl[t + j * 256]; }
            }

            const __nv_bfloat16* Kh = (const __nv_bfloat16*)(bufbase + cb * STAGE_BYTES);
            const __nv_bfloat16* Kl = Kh + KTILE * KPITCH;
            float acc[4] = {0.f, 0.f, 0.f, 0.f};
            const int nrow = w * 8 + g;
            #pragma unroll
            for (int s = 0; s < 8; ++s) {
                const int off = nrow * KPITCH + 16 * s + 2 * tg;
                uint32_t b0h = *(const uint32_t*)(Kh + off);
                uint32_t b1h = *(const uint32_t*)(Kh + off + 8);
                uint32_t b0l = *(const uint32_t*)(Kl + off);
                uint32_t b1l = *(const uint32_t*)(Kl + off + 8);
                mma16816(acc, qh[s][0], qh[s][1], qh[s][2], qh[s][3], b0h, b1h);
                mma16816(acc, qh[s][0], qh[s][1], qh[s][2], qh[s][3], b0l, b1l);
                mma16816(acc, ql[s][0], ql[s][1], ql[s][2], ql[s][3], b0h, b1h);
            }

            // epilogue: modulate + store to S
            {
                const int col = kt * KTILE + w * 8 + 2 * tg;
                const size_t r0 = adbase + (size_t)g * Ll + col;
                const size_t r1 = adbase + (size_t)(g + 8) * Ll + col;
                float2 av0 = *(const float2*)&A[r0];
                float2 dv0 = *(const float2*)&Dm[r0];
                float2 av1 = *(const float2*)&A[r1];
                float2 dv1 = *(const float2*)&Dm[r1];
                float m0 = (1.f + av0.x * wa + dv0.x * wd) * INV_SCALE;
                float m1 = (1.f + av0.y * wa + dv0.y * wd) * INV_SCALE;
                float m2 = (1.f + av1.x * wa + dv1.x * wd) * INV_SCALE;
                float m3 = (1.f + av1.y * wa + dv1.y * wd) * INV_SCALE;
                *(float2*)&S[g * SPITCH + col]       = make_float2(acc[0] * m0, acc[1] * m1);
                *(float2*)&S[(g + 8) * SPITCH + col] = make_float2(acc[2] * m2, acc[3] * m3);
            }

            if (kt + 1 < NKT) {
                uint4* dh = (uint4*)(bufbase + (1 - cb) * STAGE_BYTES);
                uint4* dl = (uint4*)(bufbase + (1 - cb) * STAGE_BYTES + KTILE * KPITCH * 2);
                #pragma unroll
                for (int j = 0; j < 4; ++j) {
                    int i = t + j * 256, r = i >> 4, c = i & 15;
                    dh[r * 17 + c] = stg[j];
                    dl[r * 17 + c] = stg[4 + j];
                }
            }
            __syncthreads();
        }
    }

    // ============ Phase 2: softmax (exp in place, keep 1/sum) ============
    {
        #pragma unroll
        for (int rsel = 0; rsel < 2; ++rsel) {
            const int rr = w + rsel * 8;
            float* row = S + rr * SPITCH;
            float m = -1e30f;
            for (int c = lane; c < Ll; c += 32) m = fmaxf(m, row[c]);
            #pragma unroll
            for (int o = 16; o > 0; o >>= 1) m = fmaxf(m, __shfl_xor_sync(0xffffffffu, m, o));
            float sum = 0.f;
            for (int c = lane; c < Ll; c += 32) {
                float e = __expf(row[c] - m);
                row[c] = e;
                sum += e;
            }
            #pragma unroll
            for (int o = 16; o > 0; o >>= 1) sum += __shfl_xor_sync(0xffffffffu, sum, o);
            if (lane == 0) s_inv[rr] = 1.f / sum;
        }
    }
    __syncthreads();

    // ============ Phase 3: write normalized attention ============
    {
        float* attn_base = attn + (bh * Ll + q0) * Ll;
        #pragma unroll 4
        for (int i = t; i < QT * Ll / 4; i += NTHREADS) {
            const int row = i >> 9;
            const int c4 = i & 511;
            const float inv = s_inv[row];
            float4 v = *(const float4*)&S[row * SPITCH + c4 * 4];
            v.x *= inv; v.y *= inv; v.z *= inv; v.w *= inv;
            ((float4*)(attn_base + (size_t)row * Ll))[c4] = v;
        }
    }
    __syncthreads();

    // ============ Phase 3.5: in-place convert S words -> packed (hi | lo<<16) ============
    {
        uint32_t* Sw = (uint32_t*)S;
        for (int i = t; i < QT * SPITCH; i += NTHREADS) {
            float x = S[i];
            __nv_bfloat16 hx = __float2bfloat16_rn(x);
            __nv_bfloat16 lx = __float2bfloat16_rn(x - __bfloat162float(hx));
            Sw[i] = (uint32_t)*(unsigned short*)&hx | ((uint32_t)*(unsigned short*)&lx << 16);
        }
    }
    __syncthreads();

    // ============ Phase 4: out = P @ V via mma ============
    {
        // preload V tile 0 (layout [d][k] in smem, pitch VPITCH bf16)
        {
            const uint4* sh = (const uint4*)(g_Vthi + vbase);
            const uint4* sl = (const uint4*)(g_Vtlo + vbase);
            #pragma unroll
            for (int j = 0; j < 4; ++j) {
                int i = t + j * 256, d = i >> 3, c = i & 7;
                stg[j]     = sh[d * 256 + c];
                stg[4 + j] = sl[d * 256 + c];
            }
            uint4* dh = (uint4*)(bufbase);
            uint4* dl = (uint4*)(bufbase + Dd * VPITCH * 2);
            #pragma unroll
            for (int j = 0; j < 4; ++j) {
                int i = t + j * 256, d = i >> 3, c = i & 7;
                dh[d * 9 + c] = stg[j];
                dl[d * 9 + c] = stg[4 + j];
            }
        }
        __syncthreads();

        float accO[2][4] = {{0.f, 0.f, 0.f, 0.f}, {0.f, 0.f, 0.f, 0.f}};
        const uint32_t* Sw = (const uint32_t*)S;

        for (int kt = 0; kt < NKT; ++kt) {
            const int cb = kt & 1;
            if (kt + 1 < NKT) {
                const uint4* sh = (const uint4*)(g_Vthi + vbase);
                const uint4* sl = (const uint4*)(g_Vtlo + vbase);
                #pragma unroll
                for (int j = 0; j < 4; ++j) {
                    int i = t + j * 256, d = i >> 3, c = i & 7;
                    stg[j]     = sh[d * 256 + (kt + 1) * 8 + c];
                    stg[4 + j] = sl[d * 256 + (kt + 1) * 8 + c];
                }
            }

            const __nv_bfloat16* Vh = (const __nv_bfloat16*)(bufbase + cb * STAGE_BYTES);
            const __nv_bfloat16* Vl = Vh + Dd * VPITCH;
            const int k0 = kt * KTILE;
            #pragma unroll
            for (int s = 0; s < 4; ++s) {
                const int kk = 16 * s + 2 * tg;
                uint2 u00 = *(const uint2*)(Sw + g * SPITCH + k0 + kk);
                uint2 u01 = *(const uint2*)(Sw + g * SPITCH + k0 + kk + 8);
                uint2 u10 = *(const uint2*)(Sw + (g + 8) * SPITCH + k0 + kk);
                uint2 u11 = *(const uint2*)(Sw + (g + 8) * SPITCH + k0 + kk + 8);
                uint32_t a0h = __byte_perm(u00.x, u00.y, 0x5410), a0l = __byte_perm(u00.x, u00.y, 0x7632);
                uint32_t a1h = __byte_perm(u10.x, u10.y, 0x5410), a1l = __byte_perm(u10.x, u10.y, 0x7632);
                uint32_t a2h = __byte_perm(u01.x, u01.y, 0x5410), a2l = __byte_perm(u01.x, u01.y, 0x7632);
                uint32_t a3h = __byte_perm(u11.x, u11.y, 0x5410), a3l = __byte_perm(u11.x, u11.y, 0x7632);
                #pragma unroll
                for (int nt = 0; nt < 2; ++nt) {
                    const int vr = (w * 16 + nt * 8 + g) * VPITCH + kk;
                    uint32_t b0h = *(const uint32_t*)(Vh + vr);
                    uint32_t b1h = *(const uint32_t*)(Vh + vr + 8);
                    uint32_t b0l = *(const uint32_t*)(Vl + vr);
                    uint32_t b1l = *(const uint32_t*)(Vl + vr + 8);
                    mma16816(accO[nt], a0h, a1h, a2h, a3h, b0h, b1h);
                    mma16816(accO[nt], a0h, a1h, a2h, a3h, b0l, b1l);
                    mma16816(accO[nt], a0l, a1l, a2l, a3l, b0h, b1h);
                }
            }

            if (kt + 1 < NKT) {
                uint4* dh = (uint4*)(bufbase + (1 - cb) * STAGE_BYTES);
                uint4* dl = (uint4*)(bufbase + (1 - cb) * STAGE_BYTES + Dd * VPITCH * 2);
                #pragma unroll
                for (int j = 0; j < 4; ++j) {
                    int i = t + j * 256, d = i >> 3, c = i & 7;
                    dh[d * 9 + c] = stg[j];
                    dl[d * 9 + c] = stg[4 + j];
                }
            }
            __syncthreads();
        }

        // epilogue: normalize + write out
        const float inv0 = s_inv[g];
        const float inv1 = s_inv[g + 8];
        float* outb = out + (bh * Ll + q0) * Dd;
        #pragma unroll
        for (int nt = 0; nt < 2; ++nt) {
            const int col = w * 16 + nt * 8 + 2 * tg;
            *(float2*)&outb[(size_t)g * Dd + col]       = make_float2(accO[nt][0] * inv0, accO[nt][1] * inv0);
            *(float2*)&outb[(size_t)(g + 8) * Dd + col] = make_float2(accO[nt][2] * inv1, accO[nt][3] * inv1);
        }
    }
}

// ---------------- launch ----------------
extern "C" void kernel_launch(void* const* d_in, const int* in_sizes, int n_in,
                              void* d_out, int out_size) {
    (void)in_sizes; (void)n_in; (void)out_size;
    const float* Q  = (const float*)d_in[0];
    const float* K  = (const float*)d_in[1];
    const float* V  = (const float*)d_in[2];
    const float* A  = (const float*)d_in[3];
    const float* Ds = (const float*)d_in[4];
    const float* wA = (const float*)d_in[5];
    const float* wD = (const float*)d_in[6];

    float* out  = (float*)d_out;
    float* attn = (float*)d_out + (size_t)Bq * Hh * Ll * Dd;

    // prep: split K and transposed V into bf16 hi/lo scratch
    prep_k_kernel<<<(unsigned)(NELEM / 4 / 256), 256>>>(K);
    {
        dim3 gv(Ll / 32, Dd / 32, Bq * Hh);
        dim3 bv(32, 8);
        prep_v_kernel<<<gv, bv>>>(V);
    }

    cudaFuncSetAttribute(msrsa_mma_kernel,
                         cudaFuncAttributeMaxDynamicSharedMemorySize, SMEM_BYTES);
    dim3 grid(Bq * Hh * (Ll / QT));   // 4096 CTAs, h innermost
    msrsa_mma_kernel<<<grid, NTHREADS, SMEM_BYTES>>>(Q, A, Ds, wA, wD, out, attn);
}

// round 4
// speedup vs baseline: 4.4189x; 2.0302x over previous
#include <cuda_runtime.h>
#include <cuda_bf16.h>
#include <stdint.h>

// MSRSA fused attention — flash-style single-pass bf16x3 tensor-core kernel.
// B=2, H=16, L=2048, D=128.
// QT=64 rows per CTA, one pass over K: logits(mma) -> modulate -> exp(l-16)
// -> attn store (unnormalized) -> PV(mma, P from logit fragments).
// Rowsums -> g_inv; rescale kernel normalizes attn afterwards.

#define Bq 2
#define Hh 16
#define Ll 2048
#define Dd 128
#define QT 64
#define KTILE 64
#define NKT 32
#define NTHREADS 256
#define INV_SCALE 0.08838834764831845f   // 1/sqrt(128)
#define EXP_OFF 16.0f

// smem layout (bytes)
#define QPB 272                  // Q plane row pitch (136 bf16)
#define KPB 272
#define VPB 144                  // V^T plane row pitch (72 bf16)
#define Q_PLANE (64 * QPB)       // 17408
#define K_PLANE (64 * KPB)       // 17408
#define V_PLANE (128 * VPB)      // 18432
#define SM_Q 0
#define SM_STG (2 * Q_PLANE)     // 34816
#define STG_V (2 * K_PLANE)      // V planes offset within stage
#define STG_SIZE (2 * K_PLANE + 2 * V_PLANE)   // 71680
#define SM_ROWSUM (SM_STG + 2 * STG_SIZE)      // 178176
#define SM_INV (SM_ROWSUM + 512)               // 178688
#define SM_RED SM_STG            // reuse stage area after main loop
#define RED_PITCH 132
#define SMEM_TOTAL (SM_INV + 256 + 16)         // 178960

#define NELEM ((size_t)Bq * Hh * Ll * Dd)

__device__ __nv_bfloat16 g_Khi[NELEM];
__device__ __nv_bfloat16 g_Klo[NELEM];
__device__ __nv_bfloat16 g_Vthi[NELEM];   // [bh][d][k]
__device__ __nv_bfloat16 g_Vtlo[NELEM];
__device__ float g_inv[(size_t)Bq * Hh * Ll];

// ---------------- helpers ----------------
__device__ __forceinline__ uint32_t s2u(const void* p) {
    return (uint32_t)__cvta_generic_to_shared(p);
}
__device__ __forceinline__ void cp16(uint32_t dst, const void* src) {
    asm volatile("cp.async.cg.shared.global [%0], [%1], 16;\n" :: "r"(dst), "l"(src));
}
__device__ __forceinline__ void ldsm4(uint32_t r[4], uint32_t addr) {
    asm volatile("ldmatrix.sync.aligned.m8n8.x4.shared.b16 {%0,%1,%2,%3}, [%4];\n"
                 : "=r"(r[0]), "=r"(r[1]), "=r"(r[2]), "=r"(r[3]) : "r"(addr));
}
__device__ __forceinline__ void mma16816(float c[4],
                                         uint32_t a0, uint32_t a1, uint32_t a2, uint32_t a3,
                                         uint32_t b0, uint32_t b1) {
    asm volatile(
        "mma.sync.aligned.m16n8k16.row.col.f32.bf16.bf16.f32 "
        "{%0,%1,%2,%3}, {%4,%5,%6,%7}, {%8,%9}, {%0,%1,%2,%3};\n"
        : "+f"(c[0]), "+f"(c[1]), "+f"(c[2]), "+f"(c[3])
        : "r"(a0), "r"(a1), "r"(a2), "r"(a3), "r"(b0), "r"(b1));
}
__device__ __forceinline__ void split2(float x, float y, uint32_t& hi, uint32_t& lo) {
    __nv_bfloat16 hx = __float2bfloat16_rn(x);
    __nv_bfloat16 hy = __float2bfloat16_rn(y);
    float rx = x - __bfloat162float(hx);
    float ry = y - __bfloat162float(hy);
    __nv_bfloat16 lx = __float2bfloat16_rn(rx);
    __nv_bfloat16 ly = __float2bfloat16_rn(ry);
    hi = (uint32_t)*(unsigned short*)&hx | ((uint32_t)*(unsigned short*)&hy << 16);
    lo = (uint32_t)*(unsigned short*)&lx | ((uint32_t)*(unsigned short*)&ly << 16);
}

// ---------------- prep kernels ----------------
__global__ void prep_k_kernel(const float* __restrict__ K) {
    size_t i = (size_t)blockIdx.x * blockDim.x + threadIdx.x;
    if (i >= NELEM / 4) return;
    float4 v = ((const float4*)K)[i];
    uint32_t h0, l0, h1, l1;
    split2(v.x, v.y, h0, l0);
    split2(v.z, v.w, h1, l1);
    ((uint2*)g_Khi)[i] = make_uint2(h0, h1);
    ((uint2*)g_Klo)[i] = make_uint2(l0, l1);
}

__global__ void prep_v_kernel(const float* __restrict__ V) {
    __shared__ float ts[32][33];
    const int tx = threadIdx.x, ty = threadIdx.y;    // (32, 8)
    const int k0 = blockIdx.x * 32;
    const int d0 = blockIdx.y * 32;
    const int bh = blockIdx.z;
    const size_t vb = (size_t)bh * Ll * Dd;
    #pragma unroll
    for (int i = 0; i < 4; ++i)
        ts[ty + 8 * i][tx] = V[vb + (size_t)(k0 + ty + 8 * i) * Dd + d0 + tx];
    __syncthreads();
    #pragma unroll
    for (int i = 0; i < 4; ++i) {
        float x = ts[tx][ty + 8 * i];
        __nv_bfloat16 h = __float2bfloat16_rn(x);
        __nv_bfloat16 l = __float2bfloat16_rn(x - __bfloat162float(h));
        size_t o = (size_t)bh * Dd * Ll + (size_t)(d0 + ty + 8 * i) * Ll + k0 + tx;
        g_Vthi[o] = h;
        g_Vtlo[o] = l;
    }
}

// ---------------- main kernel ----------------
__global__ void __launch_bounds__(NTHREADS, 1)
msrsa_flash_kernel(const float* __restrict__ Q,
                   const float* __restrict__ A,
                   const float* __restrict__ Dm,
                   const float* __restrict__ wA,
                   const float* __restrict__ wD,
                   float* __restrict__ out,
                   float* __restrict__ attn) {
    extern __shared__ char smc[];
    const uint32_t smb = s2u(smc);

    const int t = threadIdx.x;
    const int w = t >> 5;
    const int lane = t & 31;
    const int g = lane >> 2;
    const int tg = lane & 3;
    const int mg = w >> 1;        // 0..3  (m16 group)
    const int ng = w & 1;         // 0..1  (k32 chunk)
    const int m0 = mg * 16;
    const int nbase = ng * 32;

    const int bx = blockIdx.x;
    const int h = bx & (Hh - 1);
    const int qt = (bx >> 4) & 31;
    const int b = bx >> 9;
    const int q0 = qt * QT;
    const size_t bh = (size_t)(b * Hh + h);

    const float wa = wA[h];
    const float wd = wD[h];
    const size_t kbase = bh * (size_t)Ll * Dd;
    const size_t vbase = bh * (size_t)Dd * Ll;

    // ---- fill Q planes (hi/lo, pair-packed) ----
    {
        const float* Qb = Q + (bh * Ll + q0) * Dd;
        #pragma unroll
        for (int i = 0; i < 16; ++i) {
            int idx = t + i * NTHREADS;          // 4096 pairs
            int row = idx >> 6, c = idx & 63;
            float2 v = *(const float2*)(Qb + row * Dd + 2 * c);
            uint32_t hi, lo;
            split2(v.x, v.y, hi, lo);
            *(uint32_t*)(smc + SM_Q + row * QPB + c * 4) = hi;
            *(uint32_t*)(smc + SM_Q + Q_PLANE + row * QPB + c * 4) = lo;
        }
    }

    // ---- stage issue (cp.async, one commit group per tile) ----
    auto issue_stage = [&](int kt, int buf) {
        const uint32_t sb = smb + SM_STG + buf * STG_SIZE;
        const char* gkh = (const char*)(g_Khi + kbase + (size_t)kt * KTILE * Dd);
        const char* gkl = (const char*)(g_Klo + kbase + (size_t)kt * KTILE * Dd);
        #pragma unroll
        for (int j = 0; j < 4; ++j) {
            int idx = t + j * NTHREADS;          // 1024 chunks
            int row = idx >> 4, ch = idx & 15;
            cp16(sb + row * KPB + ch * 16, gkh + row * 256 + ch * 16);
            cp16(sb + K_PLANE + row * KPB + ch * 16, gkl + row * 256 + ch * 16);
        }
        const char* gvh = (const char*)(g_Vthi + vbase) + (size_t)kt * 128;
        const char* gvl = (const char*)(g_Vtlo + vbase) + (size_t)kt * 128;
        #pragma unroll
        for (int j = 0; j < 4; ++j) {
            int idx = t + j * NTHREADS;          // 1024 chunks
            int d = idx >> 3, ch = idx & 7;
            cp16(sb + STG_V + d * VPB + ch * 16, gvh + (size_t)d * (Ll * 2) + ch * 16);
            cp16(sb + STG_V + V_PLANE + d * VPB + ch * 16, gvl + (size_t)d * (Ll * 2) + ch * 16);
        }
        asm volatile("cp.async.commit_group;\n" ::: "memory");
    };

    // ldmatrix lane offsets (bytes)
    const uint32_t a_off = (uint32_t)((m0 + (lane & 7) + ((lane >> 3) & 1) * 8) * QPB
                                      + (((lane >> 4) & 1) * 8) * 2);
    const uint32_t b_off0 = (uint32_t)((nbase + ((lane >> 4) << 3) + (lane & 7)) * KPB
                                       + (((lane >> 3) & 1) * 8) * 2);
    const uint32_t b_off1 = b_off0 + 16 * KPB;
    const uint32_t v_off = (uint32_t)((((lane >> 4) << 3) + (lane & 7)) * VPB
                                      + (nbase + ((lane >> 3) & 1) * 8) * 2);
    const uint32_t qh_base = smb + SM_Q;
    const uint32_t ql_base = qh_base + Q_PLANE;

    // per-warp global row pointers
    const float* Arow_lo = A  + ((size_t)b * Ll + q0 + m0 + g) * Ll;
    const float* Drow_lo = Dm + ((size_t)b * Ll + q0 + m0 + g) * Ll;
    float* attn_lo = attn + (bh * Ll + q0 + m0 + g) * Ll;

    float accO[16][4];
    #pragma unroll
    for (int i = 0; i < 16; ++i)
        #pragma unroll
        for (int j = 0; j < 4; ++j) accO[i][j] = 0.f;
    float rs_lo = 0.f, rs_hi = 0.f;

    issue_stage(0, 0);

    for (int kt = 0; kt < NKT; ++kt) {
        if (kt + 1 < NKT) {
            issue_stage(kt + 1, (kt + 1) & 1);
            asm volatile("cp.async.wait_group 1;\n" ::: "memory");
        } else {
            asm volatile("cp.async.wait_group 0;\n" ::: "memory");
        }
        __syncthreads();

        const uint32_t kh = smb + SM_STG + (kt & 1) * STG_SIZE;
        const uint32_t kl = kh + K_PLANE;
        const uint32_t vh = kh + STG_V;
        const uint32_t vl = vh + V_PLANE;

        // ---- logits: m16 x n32 x d128 ----
        float c[4][4];
        #pragma unroll
        for (int i = 0; i < 4; ++i)
            #pragma unroll
            for (int j = 0; j < 4; ++j) c[i][j] = 0.f;

        #pragma unroll
        for (int s = 0; s < 8; ++s) {
            uint32_t ah[4], al[4], bh0[4], bh1[4], bl0[4], bl1[4];
            ldsm4(ah, qh_base + a_off + s * 32);
            ldsm4(al, ql_base + a_off + s * 32);
            ldsm4(bh0, kh + b_off0 + s * 32);
            ldsm4(bh1, kh + b_off1 + s * 32);
            ldsm4(bl0, kl + b_off0 + s * 32);
            ldsm4(bl1, kl + b_off1 + s * 32);
            #pragma unroll
            for (int j = 0; j < 4; ++j) {
                const uint32_t* bhp = (j < 2) ? bh0 : bh1;
                const uint32_t* blp = (j < 2) ? bl0 : bl1;
                const int ii = (j & 1) * 2;
                mma16816(c[j], ah[0], ah[1], ah[2], ah[3], bhp[ii], bhp[ii + 1]);
                mma16816(c[j], ah[0], ah[1], ah[2], ah[3], blp[ii], blp[ii + 1]);
                mma16816(c[j], al[0], al[1], al[2], al[3], bhp[ii], bhp[ii + 1]);
            }
        }

        // ---- modulate + exp + attn store + pack P fragments ----
        uint32_t pa_h[2][4], pa_l[2][4];
        #pragma unroll
        for (int j = 0; j < 4; ++j) {
            const int col = kt * KTILE + nbase + j * 8 + 2 * tg;
            float2 a0 = *(const float2*)(Arow_lo + col);
            float2 d0 = *(const float2*)(Drow_lo + col);
            float2 a1 = *(const float2*)(Arow_lo + 8 * Ll + col);
            float2 d1 = *(const float2*)(Drow_lo + 8 * Ll + col);
            float p00 = __expf(c[j][0] * ((1.f + a0.x * wa + d0.x * wd) * INV_SCALE) - EXP_OFF);
            float p01 = __expf(c[j][1] * ((1.f + a0.y * wa + d0.y * wd) * INV_SCALE) - EXP_OFF);
            float p10 = __expf(c[j][2] * ((1.f + a1.x * wa + d1.x * wd) * INV_SCALE) - EXP_OFF);
            float p11 = __expf(c[j][3] * ((1.f + a1.y * wa + d1.y * wd) * INV_SCALE) - EXP_OFF);
            *(float2*)(attn_lo + col) = make_float2(p00, p01);
            *(float2*)(attn_lo + 8 * Ll + col) = make_float2(p10, p11);
            rs_lo += p00 + p01;
            rs_hi += p10 + p11;
            const int kf = j >> 1, ai = (j & 1) * 2;
            split2(p00, p01, pa_h[kf][ai], pa_l[kf][ai]);
            split2(p10, p11, pa_h[kf][ai + 1], pa_l[kf][ai + 1]);
        }

        // ---- PV: A = P (m16 x k32), B = V^T (k32 x d128) ----
        #pragma unroll
        for (int kf = 0; kf < 2; ++kf) {
            #pragma unroll
            for (int q = 0; q < 8; ++q) {
                uint32_t vbh[4], vbl[4];
                const uint32_t voff = v_off + q * 16 * VPB + kf * 32;
                ldsm4(vbh, vh + voff);
                ldsm4(vbl, vl + voff);
                #pragma unroll
                for (int h2 = 0; h2 < 2; ++h2) {
                    const int ni = q * 2 + h2;
                    const int ii = h2 * 2;
                    mma16816(accO[ni], pa_h[kf][0], pa_h[kf][1], pa_h[kf][2], pa_h[kf][3],
                             vbh[ii], vbh[ii + 1]);
                    mma16816(accO[ni], pa_h[kf][0], pa_h[kf][1], pa_h[kf][2], pa_h[kf][3],
                             vbl[ii], vbl[ii + 1]);
                    mma16816(accO[ni], pa_l[kf][0], pa_l[kf][1], pa_l[kf][2], pa_l[kf][3],
                             vbh[ii], vbh[ii + 1]);
                }
            }
        }
        __syncthreads();
    }

    // ---- rowsum reduce ----
    rs_lo += __shfl_xor_sync(0xffffffffu, rs_lo, 1);
    rs_lo += __shfl_xor_sync(0xffffffffu, rs_lo, 2);
    rs_hi += __shfl_xor_sync(0xffffffffu, rs_hi, 1);
    rs_hi += __shfl_xor_sync(0xffffffffu, rs_hi, 2);
    float* rsm = (float*)(smc + SM_ROWSUM);
    if (tg == 0) {
        rsm[(m0 + g) * 2 + ng] = rs_lo;
        rsm[(m0 + g + 8) * 2 + ng] = rs_hi;
    }
    __syncthreads();
    float* sinv = (float*)(smc + SM_INV);
    if (t < QT) {
        float iv = 1.f / (rsm[t * 2] + rsm[t * 2 + 1]);
        sinv[t] = iv;
        g_inv[bh * Ll + q0 + t] = iv;
    }
    __syncthreads();

    // ---- PV cross-warp (ng) reduce + write out ----
    float* red = (float*)(smc + SM_RED) + mg * 16 * RED_PITCH;
    if (ng == 1) {
        #pragma unroll
        for (int ni = 0; ni < 16; ++ni) {
            const int col = ni * 8 + 2 * tg;
            *(float2*)&red[g * RED_PITCH + col] = make_float2(accO[ni][0], accO[ni][1]);
            *(float2*)&red[(g + 8) * RED_PITCH + col] = make_float2(accO[ni][2], accO[ni][3]);
        }
    }
    __syncthreads();
    if (ng == 0) {
        const float ivlo = sinv[m0 + g];
        const float ivhi = sinv[m0 + g + 8];
        float* olo = out + (bh * Ll + q0 + m0 + g) * Dd;
        #pragma unroll
        for (int ni = 0; ni < 16; ++ni) {
            const int col = ni * 8 + 2 * tg;
            float2 r0 = *(const float2*)&red[g * RED_PITCH + col];
            float2 r1 = *(const float2*)&red[(g + 8) * RED_PITCH + col];
            *(float2*)(olo + col) = make_float2((accO[ni][0] + r0.x) * ivlo,
                                                (accO[ni][1] + r0.y) * ivlo);
            *(float2*)(olo + 8 * Dd + col) = make_float2((accO[ni][2] + r1.x) * ivhi,
                                                         (accO[ni][3] + r1.y) * ivhi);
        }
    }
}

// ---------------- rescale kernel (normalize attn) ----------------
__global__ void __launch_bounds__(256)
rescale_kernel(float* __restrict__ attn) {
    const size_t row = blockIdx.x;
    const float iv = g_inv[row];
    float4* p = (float4*)(attn + row * Ll);
    #pragma unroll
    for (int i = 0; i < 2; ++i) {
        int idx = threadIdx.x + i * 256;
        float4 v = p[idx];
        v.x *= iv; v.y *= iv; v.z *= iv; v.w *= iv;
        p[idx] = v;
    }
}

// ---------------- launch ----------------
extern "C" void kernel_launch(void* const* d_in, const int* in_sizes, int n_in,
                              void* d_out, int out_size) {
    (void)in_sizes; (void)n_in; (void)out_size;
    const float* Q  = (const float*)d_in[0];
    const float* K  = (const float*)d_in[1];
    const float* V  = (const float*)d_in[2];
    const float* A  = (const float*)d_in[3];
    const float* Ds = (const float*)d_in[4];
    const float* wA = (const float*)d_in[5];
    const float* wD = (const float*)d_in[6];

    float* out  = (float*)d_out;
    float* attn = (float*)d_out + (size_t)Bq * Hh * Ll * Dd;

    prep_k_kernel<<<(unsigned)(NELEM / 4 / 256), 256>>>(K);
    {
        dim3 gv(Ll / 32, Dd / 32, Bq * Hh);
        dim3 bv(32, 8);
        prep_v_kernel<<<gv, bv>>>(V);
    }

    cudaFuncSetAttribute(msrsa_flash_kernel,
                         cudaFuncAttributeMaxDynamicSharedMemorySize, SMEM_TOTAL);
    dim3 grid(Bq * Hh * (Ll / QT));   // 1024 CTAs, h innermost
    msrsa_flash_kernel<<<grid, NTHREADS, SMEM_TOTAL>>>(Q, A, Ds, wA, wD, out, attn);

    rescale_kernel<<<Bq * Hh * Ll, 256>>>(attn);
}